// round 14
// baseline (speedup 1.0000x reference)
#include <cuda_runtime.h>
#include <cstdint>

typedef unsigned long long u64;
typedef unsigned int u32;

#define NP 131072
#define NC 128
#define TPB 128
#define NBLK (NP / TPB)   // 1024

__device__ __align__(16) float g_params[NC * 12];
__device__ float g_partial[NBLK];
__device__ u32 g_done = 0;   // self-resetting via atomicInc wrap

// ---------------------------------------------------------------------------
// Setup: 128 blocks (1/center); 6 threads do the 6 fp64 trig calls in parallel.
// Numerics identical to passing R4/R6/R7/R11/R12/R13.
// ---------------------------------------------------------------------------
__global__ void setup_kernel(const float* __restrict__ centers,
                             const float* __restrict__ radii,
                             const float* __restrict__ rot) {
    __shared__ float strig[6];
    int t = threadIdx.x;
    int c = blockIdx.x;
    if (t < 6) {
        int axis = t >> 1;
        double a = (double)rot[c * 3 + axis];
        strig[t] = (t & 1) ? (float)sin(a) : (float)cos(a);
    }
    __syncthreads();
    if (t != 0) return;

    float d[3];
#pragma unroll
    for (int i = 0; i < 3; i++)
        d[i] = __fdiv_rn(1.0f, __fadd_rn(fabsf(radii[c * 3 + i]), 1e-8f));

    float cx = strig[0], sx = strig[1];
    float cy = strig[2], sy = strig[3];
    float cz = strig[4], sz = strig[5];

    float R[3][3];
    R[0][0] = __fmul_rn(cz, cy);
    R[0][1] = __fsub_rn(__fmul_rn(__fmul_rn(cz, sy), sx), __fmul_rn(sz, cx));
    R[0][2] = __fadd_rn(__fmul_rn(__fmul_rn(cz, sy), cx), __fmul_rn(sz, sx));
    R[1][0] = __fmul_rn(sz, cy);
    R[1][1] = __fadd_rn(__fmul_rn(__fmul_rn(sz, sy), sx), __fmul_rn(cz, cx));
    R[1][2] = __fsub_rn(__fmul_rn(__fmul_rn(sz, sy), cx), __fmul_rn(cz, sx));
    R[2][0] = -sy;
    R[2][1] = __fmul_rn(cy, sx);
    R[2][2] = __fmul_rn(cy, cx);

    float tmp[3][3];
#pragma unroll
    for (int a = 0; a < 3; a++)
#pragma unroll
        for (int b = 0; b < 3; b++)
            tmp[a][b] = __fmul_rn(R[a][b], d[b]);

    float M[3][3];
#pragma unroll
    for (int a = 0; a < 3; a++)
#pragma unroll
        for (int cc = 0; cc < 3; cc++)
            M[a][cc] = __fadd_rn(__fadd_rn(__fmul_rn(tmp[a][0], R[cc][0]),
                                           __fmul_rn(tmp[a][1], R[cc][1])),
                                 __fmul_rn(tmp[a][2], R[cc][2]));

    float* oA = g_params + c * 12;
    oA[0] = centers[c * 3 + 0];
    oA[1] = centers[c * 3 + 1];
    oA[2] = centers[c * 3 + 2];
    oA[3]  = M[0][0];
    oA[4]  = M[1][0]; oA[5]  = M[2][0]; oA[6]  = M[0][1]; oA[7]  = M[1][1];
    oA[8]  = M[2][1]; oA[9]  = M[0][2]; oA[10] = M[1][2]; oA[11] = M[2][2];
}

// ---------------------------------------------------------------------------
// u32 sorting network, ascending — each CE is 2x IMNMX. All static indexing.
// ---------------------------------------------------------------------------
__device__ __forceinline__ void ce_asc(u32& a, u32& b) {
    u32 lo = min(a, b);
    u32 hi = max(a, b);
    a = lo; b = hi;
}

__device__ __forceinline__ void sort16_asc(u32 v[16]) {
#pragma unroll
    for (int p = 1; p < 16; p <<= 1) {
#pragma unroll
        for (int k = p; k >= 1; k >>= 1) {
#pragma unroll
            for (int j = k & (p - 1); j + k < 16; j += 2 * k) {
#pragma unroll
                for (int i = 0; i < k && (i + j + k) < 16; i++) {
                    if (((i + j) / (2 * p)) == ((i + j + k) / (2 * p))) {
                        ce_asc(v[i + j], v[i + j + k]);
                    }
                }
            }
        }
    }
}

// R asc, C asc -> R = 16 smallest of union; (r17, r18) = two smallest
// discarded keys (streaming branchless insert).
template <bool CLEANUP>
__device__ __forceinline__ void merge16_asc(u32 R[16], const u32 C[16],
                                            u32& r17, u32& r18) {
#pragma unroll
    for (int i = 0; i < 16; i++) {
        u32 b = C[15 - i];
        u32 mx = max(R[i], b);
        R[i] = min(R[i], b);
        u32 t = max(r17, mx);
        r17 = min(r17, mx);
        r18 = min(r18, t);
    }
    if (CLEANUP) {
#pragma unroll
        for (int d = 8; d >= 1; d >>= 1) {
#pragma unroll
            for (int i = 0; i < 16; i++) {
                if ((i & d) == 0) ce_asc(R[i], R[i + d]);
            }
        }
    }
}

__device__ __forceinline__ float ex2_fast(float x) {
    float r;
    asm("ex2.approx.f32 %0, %1;" : "=f"(r) : "f"(x));
    return r;
}

// Quadratic form — bit-identical grouping to all passing kernels.
__device__ __forceinline__ float quadA(const float4* sA, int c,
                                       float x, float y, float z) {
    float4 a0 = sA[c * 3 + 0];
    float4 a1 = sA[c * 3 + 1];
    float4 a2 = sA[c * 3 + 2];
    float dx = x - a0.x, dy = y - a0.y, dz = z - a0.z;
    float t0 = fmaf(dz, a1.y, fmaf(dy, a1.x, __fmul_rn(dx, a0.w)));
    float t1 = fmaf(dz, a2.x, fmaf(dy, a1.w, __fmul_rn(dx, a1.z)));
    float t2 = fmaf(dz, a2.w, fmaf(dy, a2.z, __fmul_rn(dx, a2.y)));
    return __fadd_rn(__fadd_rn(__fmul_rn(t0, dx), __fmul_rn(t1, dy)),
                     __fmul_rn(t2, dz));
}

// ---------------------------------------------------------------------------
// Main: one thread per point. Keys = (qbits & ~0x7F) | idx.
// Boundary-tie resolution is O(1): exact q for the 16 R entries (reused as
// gather weights via smem), masked-max in the boundary bucket, swap in r17's
// center iff smaller. Full rescan only when trunc(r18) also ties (~0.04%/pt).
// ---------------------------------------------------------------------------
__global__ void __launch_bounds__(TPB, 7)
main_kernel(const float* __restrict__ xyz,
            const float4* __restrict__ rgbs,
            const float* __restrict__ dists,
            const float* __restrict__ centers,
            float* __restrict__ out, int out_size) {
    __shared__ float4 sA[NC * 3];                           // 6 KB
    __shared__ __align__(16) unsigned char slist[TPB * 16]; // 2 KB indices
    __shared__ float sqv[TPB * 16];                         // 8 KB exact q
    __shared__ u64 sbucket[TPB * 8];                        // 8 KB (rare path)
    __shared__ float sred[TPB];
    __shared__ bool sLast;

    int tid = threadIdx.x;
#pragma unroll
    for (int i = tid; i < NC * 3; i += TPB)
        sA[i] = reinterpret_cast<const float4*>(g_params)[i];
    __syncthreads();

    int p = blockIdx.x * TPB + tid;
    float x = xyz[3 * p + 0];
    float y = xyz[3 * p + 1];
    float z = xyz[3 * p + 2];

    u32 R[16];
    u32 r17 = 0xFFFFFFFFu, r18 = 0xFFFFFFFFu;
    float pen = 0.0f;
    const float CEXP = -0.72134752044448170f;  // -0.5*log2(e)
    const float K_ADD = 2.3219280948873623f;   // log2(5)

    // ---- Pass 1: scalar q for all centers; sort (truncq|idx) keys ----
#pragma unroll 1
    for (int base = 0; base < 8; base++) {
        u32 C[16];
#pragma unroll
        for (int j = 0; j < 16; j++) {
            int c = base * 16 + j;
            float q = quadA(sA, c, x, y, z);
            float e = ex2_fast(fmaf(q, CEXP, K_ADD));
            pen += fmaxf(e - 0.01f, 0.0f);
            u32 qb = __float_as_uint(fmaxf(q, 0.0f));
            C[j] = (qb & 0xFFFFFF80u) | (u32)c;
        }
        sort16_asc(C);
        if (base == 0) {
#pragma unroll
            for (int i = 0; i < 16; i++) R[i] = C[i];
        } else if (base < 7) {
            merge16_asc<true>(R, C, r17, r18);
        } else {
            merge16_asc<false>(R, C, r17, r18);  // final: set only
        }
    }

    // boundary key (16th by (truncq,idx)) via max-tree
    u32 tq = R[0];
#pragma unroll
    for (int i = 1; i < 16; i++) tq = max(tq, R[i]);
    u32 btr = tq & 0xFFFFFF80u;

    // ---- O(1) resolution: exact q for all 16 R entries (also = weights) ----
    unsigned char* ml = slist + tid * 16;
    float* qv = sqv + tid * 16;
    u64 kmax = 0;
    u32 posmax = 0;
#pragma unroll
    for (int i = 0; i < 16; i++) {
        u32 c = R[i] & 0x7Fu;
        float q = quadA(sA, (int)c, x, y, z);
        float qc = fmaxf(q, 0.0f);
        ml[i] = (unsigned char)c;   // static STS
        qv[i] = qc;                 // static STS
        u64 K = ((u64)__float_as_uint(qc) << 7) | c;
        bool inb = (R[i] & 0xFFFFFF80u) == btr;
        u64 Km = inb ? K : 0ull;
        bool gt = Km > kmax;
        kmax = gt ? Km : kmax;
        posmax = gt ? (u32)i : posmax;
    }

    bool tie17 = ((r17 ^ tq) & 0xFFFFFF80u) == 0u;
    bool tie18 = ((r18 ^ tq) & 0xFFFFFF80u) == 0u;

    if (tie17 && !tie18) {
        // single outside candidate: r17's center
        u32 c17 = r17 & 0x7Fu;
        float q17 = quadA(sA, (int)c17, x, y, z);
        float qc17 = fmaxf(q17, 0.0f);
        u64 K17 = ((u64)__float_as_uint(qc17) << 7) | c17;
        if (K17 < kmax) {
            ml[posmax] = (unsigned char)c17;  // dynamic smem store: fine
            qv[posmax] = qc17;
        }
    } else if (tie17 && tie18) {
        // ---- Very rare: full exact rescan + in-bucket selection ----
        u64* myb = sbucket + tid * 8;
        int m = 0, nb = 0;
#pragma unroll 1
        for (int c = 0; c < NC; c++) {
            float q = quadA(sA, c, x, y, z);
            float qc = fmaxf(q, 0.0f);
            u32 qb = __float_as_uint(qc);
            u32 t = qb & 0xFFFFFF80u;
            if (t < btr) {
                ml[m] = (unsigned char)c;
                qv[m] = qc;
                m++;
            } else if (t == btr && nb < 8) {
                myb[nb] = (((u64)qb << 7) | (u32)c) + 1ull;
                nb++;
            }
        }
        u64 prev = 0ull;
#pragma unroll 1
        for (int r = m; r < 16; r++) {
            u64 best = ~0ull;
#pragma unroll 1
            for (int i = 0; i < nb; i++) {
                u64 k = myb[i];
                if (k > prev && k < best) best = k;
            }
            prev = best;
            u64 bm1 = best - 1ull;
            ml[r] = (unsigned char)(bm1 & 0x7Fu);
            qv[r] = __uint_as_float((u32)(bm1 >> 7));
        }
    }

    // ---- Gather: weights from stored exact q (static smem reads) ----
    float dp = dists[p];
    const float LOG2E = 1.4426950408889634f;
    float sumw = 0.0f;
    float o0 = 0.0f, o1 = 0.0f, o2 = 0.0f, o3 = 0.0f;
#pragma unroll
    for (int i = 0; i < 16; i++) {
        int c = (int)ml[i];
        float qc = qv[i];
        float w = __fmul_rn(5.0f, ex2_fast(__fmul_rn(qc, CEXP)));
        w = (w >= 0.01f) ? w : 0.0f;
        sumw += w;
        if (w > 0.0f) {
            float4 g = __ldg(&rgbs[(size_t)c * NP + p]);
            float alpha = 1.0f - ex2_fast(fmaxf(g.w, 0.0f) * dp * (-LOG2E));
            o0 = fmaf(w, g.x, o0);
            o1 = fmaf(w, g.y, o1);
            o2 = fmaf(w, g.z, o2);
            o3 = fmaf(w, alpha, o3);
        }
    }
    float inv = __fdiv_rn(1.0f, __fadd_rn(sumw, 1e-7f));
    reinterpret_cast<float4*>(out)[p] =
        make_float4(o0 * inv, o1 * inv, o2 * inv, o3 * inv);

    // ---- deterministic block reduction of penalty ----
    sred[tid] = pen;
    __syncthreads();
#pragma unroll
    for (int s = TPB / 2; s > 0; s >>= 1) {
        if (tid < s) sred[tid] += sred[tid + s];
        __syncthreads();
    }
    if (tid == 0) {
        g_partial[blockIdx.x] = sred[0];
        __threadfence();
        u32 old = atomicInc(&g_done, NBLK - 1);
        sLast = (old == NBLK - 1);
    }
    __syncthreads();

    // ---- Last block: finalize pen (deterministic fixed-order sum) ----
    if (sLast) {
        __shared__ double sd[TPB];
        double s = 0.0;
#pragma unroll
        for (int i = 0; i < NBLK / TPB; i++)
            s += (double)g_partial[tid * (NBLK / TPB) + i];
        sd[tid] = s;
        __syncthreads();
        if (tid == 0) {
            double tot = 0.0;
            for (int i = 0; i < TPB; i++) tot += sd[i];
            float bbox = 0.0f;
            for (int i = 0; i < NC * 3; i++) {
                float val = centers[i];
                bbox += fmaxf(val - 0.5f, 0.0f) + fmaxf(-0.5f - val, 0.0f);
            }
            float pv = (float)(0.001 * tot / (double)NP) + bbox;
            if (out_size > 4 * NP) {
                out[4 * NP] = pv;
                out[out_size - 1] = pv;
            }
        }
    }
}

// ---------------------------------------------------------------------------
extern "C" void kernel_launch(void* const* d_in, const int* in_sizes, int n_in,
                              void* d_out, int out_size) {
    const float* xyz = nullptr;
    const float* dists = nullptr;
    const float4* rgbs = nullptr;
    const float* small3[3] = {nullptr, nullptr, nullptr};
    int nsmall = 0;
    for (int i = 0; i < n_in; i++) {
        int sz = in_sizes[i];
        if (sz == NP * 3)                xyz   = (const float*)d_in[i];
        else if (sz == NC * NP * 4)      rgbs  = (const float4*)d_in[i];
        else if (sz == NP)               dists = (const float*)d_in[i];
        else if (sz == NC * 3 && nsmall < 3) small3[nsmall++] = (const float*)d_in[i];
    }
    const float* centers = small3[0];
    const float* radii   = small3[1];
    const float* rots    = small3[2];

    setup_kernel<<<NC, 8>>>(centers, radii, rots);
    main_kernel<<<NBLK, TPB>>>(xyz, rgbs, dists, centers, (float*)d_out, out_size);
}

// round 15
// speedup vs baseline: 1.0524x; 1.0524x over previous
#include <cuda_runtime.h>
#include <cstdint>

typedef unsigned long long u64;
typedef unsigned int u32;

#define NP 131072
#define NC 128
#define TPB 128
#define NBLK (NP / TPB)   // 1024

__device__ __align__(16) float g_params[NC * 12];
__device__ float g_partial[NBLK];
__device__ u32 g_done = 0;   // self-resetting via atomicInc wrap

// ---------------------------------------------------------------------------
// Setup: 128 blocks (1/center); 6 threads do the 6 fp64 trig calls in parallel.
// Numerics identical to all passing kernels.
// ---------------------------------------------------------------------------
__global__ void setup_kernel(const float* __restrict__ centers,
                             const float* __restrict__ radii,
                             const float* __restrict__ rot) {
    __shared__ float strig[6];
    int t = threadIdx.x;
    int c = blockIdx.x;
    if (t < 6) {
        int axis = t >> 1;
        double a = (double)rot[c * 3 + axis];
        strig[t] = (t & 1) ? (float)sin(a) : (float)cos(a);
    }
    __syncthreads();
    if (t != 0) return;

    float d[3];
#pragma unroll
    for (int i = 0; i < 3; i++)
        d[i] = __fdiv_rn(1.0f, __fadd_rn(fabsf(radii[c * 3 + i]), 1e-8f));

    float cx = strig[0], sx = strig[1];
    float cy = strig[2], sy = strig[3];
    float cz = strig[4], sz = strig[5];

    float R[3][3];
    R[0][0] = __fmul_rn(cz, cy);
    R[0][1] = __fsub_rn(__fmul_rn(__fmul_rn(cz, sy), sx), __fmul_rn(sz, cx));
    R[0][2] = __fadd_rn(__fmul_rn(__fmul_rn(cz, sy), cx), __fmul_rn(sz, sx));
    R[1][0] = __fmul_rn(sz, cy);
    R[1][1] = __fadd_rn(__fmul_rn(__fmul_rn(sz, sy), sx), __fmul_rn(cz, cx));
    R[1][2] = __fsub_rn(__fmul_rn(__fmul_rn(sz, sy), cx), __fmul_rn(cz, sx));
    R[2][0] = -sy;
    R[2][1] = __fmul_rn(cy, sx);
    R[2][2] = __fmul_rn(cy, cx);

    float tmp[3][3];
#pragma unroll
    for (int a = 0; a < 3; a++)
#pragma unroll
        for (int b = 0; b < 3; b++)
            tmp[a][b] = __fmul_rn(R[a][b], d[b]);

    float M[3][3];
#pragma unroll
    for (int a = 0; a < 3; a++)
#pragma unroll
        for (int cc = 0; cc < 3; cc++)
            M[a][cc] = __fadd_rn(__fadd_rn(__fmul_rn(tmp[a][0], R[cc][0]),
                                           __fmul_rn(tmp[a][1], R[cc][1])),
                                 __fmul_rn(tmp[a][2], R[cc][2]));

    float* oA = g_params + c * 12;
    oA[0] = centers[c * 3 + 0];
    oA[1] = centers[c * 3 + 1];
    oA[2] = centers[c * 3 + 2];
    oA[3]  = M[0][0];
    oA[4]  = M[1][0]; oA[5]  = M[2][0]; oA[6]  = M[0][1]; oA[7]  = M[1][1];
    oA[8]  = M[2][1]; oA[9]  = M[0][2]; oA[10] = M[1][2]; oA[11] = M[2][2];
}

// ---------------------------------------------------------------------------
// u32 sorting network, ascending — each CE is 2x IMNMX. All static indexing.
// ---------------------------------------------------------------------------
__device__ __forceinline__ void ce_asc(u32& a, u32& b) {
    u32 lo = min(a, b);
    u32 hi = max(a, b);
    a = lo; b = hi;
}

__device__ __forceinline__ void sort16_asc(u32 v[16]) {
#pragma unroll
    for (int p = 1; p < 16; p <<= 1) {
#pragma unroll
        for (int k = p; k >= 1; k >>= 1) {
#pragma unroll
            for (int j = k & (p - 1); j + k < 16; j += 2 * k) {
#pragma unroll
                for (int i = 0; i < k && (i + j + k) < 16; i++) {
                    if (((i + j) / (2 * p)) == ((i + j + k) / (2 * p))) {
                        ce_asc(v[i + j], v[i + j + k]);
                    }
                }
            }
        }
    }
}

// R asc, C asc -> R = 16 smallest of union; (r17, r18) = two smallest
// discarded keys (streaming branchless insert).
template <bool CLEANUP>
__device__ __forceinline__ void merge16_asc(u32 R[16], const u32 C[16],
                                            u32& r17, u32& r18) {
#pragma unroll
    for (int i = 0; i < 16; i++) {
        u32 b = C[15 - i];
        u32 mx = max(R[i], b);
        R[i] = min(R[i], b);
        u32 t = max(r17, mx);
        r17 = min(r17, mx);
        r18 = min(r18, t);
    }
    if (CLEANUP) {
#pragma unroll
        for (int d = 8; d >= 1; d >>= 1) {
#pragma unroll
            for (int i = 0; i < 16; i++) {
                if ((i & d) == 0) ce_asc(R[i], R[i + d]);
            }
        }
    }
}

__device__ __forceinline__ float ex2_fast(float x) {
    float r;
    asm("ex2.approx.f32 %0, %1;" : "=f"(r) : "f"(x));
    return r;
}

// Quadratic form — bit-identical grouping to all passing kernels.
__device__ __forceinline__ float quadA(const float4* sA, int c,
                                       float x, float y, float z) {
    float4 a0 = sA[c * 3 + 0];
    float4 a1 = sA[c * 3 + 1];
    float4 a2 = sA[c * 3 + 2];
    float dx = x - a0.x, dy = y - a0.y, dz = z - a0.z;
    float t0 = fmaf(dz, a1.y, fmaf(dy, a1.x, __fmul_rn(dx, a0.w)));
    float t1 = fmaf(dz, a2.x, fmaf(dy, a1.w, __fmul_rn(dx, a1.z)));
    float t2 = fmaf(dz, a2.w, fmaf(dy, a2.z, __fmul_rn(dx, a2.y)));
    return __fadd_rn(__fadd_rn(__fmul_rn(t0, dx), __fmul_rn(t1, dy)),
                     __fmul_rn(t2, dz));
}

// ---------------------------------------------------------------------------
// Main: one thread per point. Keys = (qbits & ~0x7F) | idx.
// Selected (index, exact-q) live in REGISTERS with static indexing only;
// smem is touched solely by the very rare tie18 full-rescan path.
// ---------------------------------------------------------------------------
__global__ void __launch_bounds__(TPB, 7)
main_kernel(const float* __restrict__ xyz,
            const float4* __restrict__ rgbs,
            const float* __restrict__ dists,
            const float* __restrict__ centers,
            float* __restrict__ out, int out_size) {
    __shared__ float4 sA[NC * 3];                           // 6 KB
    __shared__ __align__(16) unsigned char slist[TPB * 16]; // 2 KB (rare path)
    __shared__ float sqv[TPB * 16];                         // 8 KB (rare path)
    __shared__ u64 sbucket[TPB * 8];                        // 8 KB (rare path)
    __shared__ float sred[TPB];
    __shared__ bool sLast;

    int tid = threadIdx.x;
#pragma unroll
    for (int i = tid; i < NC * 3; i += TPB)
        sA[i] = reinterpret_cast<const float4*>(g_params)[i];
    __syncthreads();

    int p = blockIdx.x * TPB + tid;
    float x = xyz[3 * p + 0];
    float y = xyz[3 * p + 1];
    float z = xyz[3 * p + 2];

    u32 R[16];
    u32 r17 = 0xFFFFFFFFu, r18 = 0xFFFFFFFFu;
    float pen = 0.0f;
    const float CEXP = -0.72134752044448170f;  // -0.5*log2(e)
    const float K_ADD = 2.3219280948873623f;   // log2(5)

    // ---- Pass 1: scalar q for all centers; sort (truncq|idx) keys ----
#pragma unroll 1
    for (int base = 0; base < 8; base++) {
        u32 C[16];
#pragma unroll
        for (int j = 0; j < 16; j++) {
            int c = base * 16 + j;
            float q = quadA(sA, c, x, y, z);
            float e = ex2_fast(fmaf(q, CEXP, K_ADD));
            pen += fmaxf(e - 0.01f, 0.0f);
            u32 qb = __float_as_uint(fmaxf(q, 0.0f));
            C[j] = (qb & 0xFFFFFF80u) | (u32)c;
        }
        sort16_asc(C);
        if (base == 0) {
#pragma unroll
            for (int i = 0; i < 16; i++) R[i] = C[i];
        } else if (base < 7) {
            merge16_asc<true>(R, C, r17, r18);
        } else {
            merge16_asc<false>(R, C, r17, r18);  // final: set only
        }
    }

    // boundary key (16th by (truncq,idx)) via max-tree
    u32 tq = R[0];
#pragma unroll
    for (int i = 1; i < 16; i++) tq = max(tq, R[i]);
    u32 btr = tq & 0xFFFFFF80u;

    // ---- Exact q for all 16 R entries, kept in REGISTERS (static idx) ----
    u32 creg[16];
    float qreg[16];
    u64 kmax = 0;
    u32 posmax = 0;
#pragma unroll
    for (int i = 0; i < 16; i++) {
        u32 c = R[i] & 0x7Fu;
        float q = quadA(sA, (int)c, x, y, z);
        float qc = fmaxf(q, 0.0f);
        creg[i] = c;
        qreg[i] = qc;
        u64 K = ((u64)__float_as_uint(qc) << 7) | c;
        bool inb = (R[i] & 0xFFFFFF80u) == btr;
        u64 Km = inb ? K : 0ull;
        bool gt = Km > kmax;
        kmax = gt ? Km : kmax;
        posmax = gt ? (u32)i : posmax;
    }

    bool tie17 = ((r17 ^ tq) & 0xFFFFFF80u) == 0u;
    bool tie18 = ((r18 ^ tq) & 0xFFFFFF80u) == 0u;

    if (tie17 && !tie18) {
        // single outside candidate: r17's center — predicated static swap
        u32 c17 = r17 & 0x7Fu;
        float q17 = quadA(sA, (int)c17, x, y, z);
        float qc17 = fmaxf(q17, 0.0f);
        u64 K17 = ((u64)__float_as_uint(qc17) << 7) | c17;
        bool swap = K17 < kmax;
#pragma unroll
        for (int i = 0; i < 16; i++) {
            bool sel = swap && ((u32)i == posmax);
            creg[i] = sel ? c17 : creg[i];
            qreg[i] = sel ? qc17 : qreg[i];
        }
    } else if (tie17 && tie18) {
        // ---- Very rare: full exact rescan + in-bucket selection (smem) ----
        unsigned char* ml = slist + tid * 16;
        float* qv = sqv + tid * 16;
        u64* myb = sbucket + tid * 8;
        int m = 0, nb = 0;
#pragma unroll 1
        for (int c = 0; c < NC; c++) {
            float q = quadA(sA, c, x, y, z);
            float qc = fmaxf(q, 0.0f);
            u32 qb = __float_as_uint(qc);
            u32 t = qb & 0xFFFFFF80u;
            if (t < btr) {
                ml[m] = (unsigned char)c;
                qv[m] = qc;
                m++;
            } else if (t == btr && nb < 8) {
                myb[nb] = (((u64)qb << 7) | (u32)c) + 1ull;
                nb++;
            }
        }
        u64 prev = 0ull;
#pragma unroll 1
        for (int r = m; r < 16; r++) {
            u64 best = ~0ull;
#pragma unroll 1
            for (int i = 0; i < nb; i++) {
                u64 k = myb[i];
                if (k > prev && k < best) best = k;
            }
            prev = best;
            u64 bm1 = best - 1ull;
            ml[r] = (unsigned char)(bm1 & 0x7Fu);
            qv[r] = __uint_as_float((u32)(bm1 >> 7));
        }
        // static copy-back into registers
#pragma unroll
        for (int i = 0; i < 16; i++) {
            creg[i] = (u32)ml[i];
            qreg[i] = qv[i];
        }
    }

    // ---- Gather: weights from register-resident exact q ----
    float dp = dists[p];
    const float LOG2E = 1.4426950408889634f;
    float sumw = 0.0f;
    float o0 = 0.0f, o1 = 0.0f, o2 = 0.0f, o3 = 0.0f;
#pragma unroll
    for (int i = 0; i < 16; i++) {
        float w = __fmul_rn(5.0f, ex2_fast(__fmul_rn(qreg[i], CEXP)));
        w = (w >= 0.01f) ? w : 0.0f;
        sumw += w;
        if (w > 0.0f) {
            float4 g = __ldg(&rgbs[(size_t)creg[i] * NP + p]);
            float alpha = 1.0f - ex2_fast(fmaxf(g.w, 0.0f) * dp * (-LOG2E));
            o0 = fmaf(w, g.x, o0);
            o1 = fmaf(w, g.y, o1);
            o2 = fmaf(w, g.z, o2);
            o3 = fmaf(w, alpha, o3);
        }
    }
    float inv = __fdiv_rn(1.0f, __fadd_rn(sumw, 1e-7f));
    reinterpret_cast<float4*>(out)[p] =
        make_float4(o0 * inv, o1 * inv, o2 * inv, o3 * inv);

    // ---- deterministic block reduction of penalty ----
    sred[tid] = pen;
    __syncthreads();
#pragma unroll
    for (int s = TPB / 2; s > 0; s >>= 1) {
        if (tid < s) sred[tid] += sred[tid + s];
        __syncthreads();
    }
    if (tid == 0) {
        g_partial[blockIdx.x] = sred[0];
        __threadfence();
        u32 old = atomicInc(&g_done, NBLK - 1);
        sLast = (old == NBLK - 1);
    }
    __syncthreads();

    // ---- Last block: finalize pen (deterministic fixed-order sum) ----
    if (sLast) {
        __shared__ double sd[TPB];
        double s = 0.0;
#pragma unroll
        for (int i = 0; i < NBLK / TPB; i++)
            s += (double)g_partial[tid * (NBLK / TPB) + i];
        sd[tid] = s;
        __syncthreads();
        if (tid == 0) {
            double tot = 0.0;
            for (int i = 0; i < TPB; i++) tot += sd[i];
            float bbox = 0.0f;
            for (int i = 0; i < NC * 3; i++) {
                float val = centers[i];
                bbox += fmaxf(val - 0.5f, 0.0f) + fmaxf(-0.5f - val, 0.0f);
            }
            float pv = (float)(0.001 * tot / (double)NP) + bbox;
            if (out_size > 4 * NP) {
                out[4 * NP] = pv;
                out[out_size - 1] = pv;
            }
        }
    }
}

// ---------------------------------------------------------------------------
extern "C" void kernel_launch(void* const* d_in, const int* in_sizes, int n_in,
                              void* d_out, int out_size) {
    const float* xyz = nullptr;
    const float* dists = nullptr;
    const float4* rgbs = nullptr;
    const float* small3[3] = {nullptr, nullptr, nullptr};
    int nsmall = 0;
    for (int i = 0; i < n_in; i++) {
        int sz = in_sizes[i];
        if (sz == NP * 3)                xyz   = (const float*)d_in[i];
        else if (sz == NC * NP * 4)      rgbs  = (const float4*)d_in[i];
        else if (sz == NP)               dists = (const float*)d_in[i];
        else if (sz == NC * 3 && nsmall < 3) small3[nsmall++] = (const float*)d_in[i];
    }
    const float* centers = small3[0];
    const float* radii   = small3[1];
    const float* rots    = small3[2];

    setup_kernel<<<NC, 8>>>(centers, radii, rots);
    main_kernel<<<NBLK, TPB>>>(xyz, rgbs, dists, centers, (float*)d_out, out_size);
}

// round 16
// speedup vs baseline: 1.0684x; 1.0152x over previous
#include <cuda_runtime.h>
#include <cstdint>

typedef unsigned long long u64;
typedef unsigned int u32;

#define NP 131072
#define NC 128
#define TPB 128
#define PPB (TPB / 2)        // 64 points per block (2 threads per point)
#define NBLK (NP / PPB)      // 2048

__device__ __align__(16) float g_params[NC * 12];
__device__ float g_partial[NBLK];
__device__ u32 g_done = 0;   // self-resetting via atomicInc wrap

// ---------------------------------------------------------------------------
// Setup: 128 blocks (1/center); 6 threads do the 6 fp64 trig calls in parallel.
// Numerics identical to all passing kernels (FROZEN — selection depends on it).
// ---------------------------------------------------------------------------
__global__ void setup_kernel(const float* __restrict__ centers,
                             const float* __restrict__ radii,
                             const float* __restrict__ rot) {
    __shared__ float strig[6];
    int t = threadIdx.x;
    int c = blockIdx.x;
    if (t < 6) {
        int axis = t >> 1;
        double a = (double)rot[c * 3 + axis];
        strig[t] = (t & 1) ? (float)sin(a) : (float)cos(a);
    }
    __syncthreads();
    if (t != 0) return;

    float d[3];
#pragma unroll
    for (int i = 0; i < 3; i++)
        d[i] = __fdiv_rn(1.0f, __fadd_rn(fabsf(radii[c * 3 + i]), 1e-8f));

    float cx = strig[0], sx = strig[1];
    float cy = strig[2], sy = strig[3];
    float cz = strig[4], sz = strig[5];

    float R[3][3];
    R[0][0] = __fmul_rn(cz, cy);
    R[0][1] = __fsub_rn(__fmul_rn(__fmul_rn(cz, sy), sx), __fmul_rn(sz, cx));
    R[0][2] = __fadd_rn(__fmul_rn(__fmul_rn(cz, sy), cx), __fmul_rn(sz, sx));
    R[1][0] = __fmul_rn(sz, cy);
    R[1][1] = __fadd_rn(__fmul_rn(__fmul_rn(sz, sy), sx), __fmul_rn(cz, cx));
    R[1][2] = __fsub_rn(__fmul_rn(__fmul_rn(sz, sy), cx), __fmul_rn(cz, sx));
    R[2][0] = -sy;
    R[2][1] = __fmul_rn(cy, sx);
    R[2][2] = __fmul_rn(cy, cx);

    float tmp[3][3];
#pragma unroll
    for (int a = 0; a < 3; a++)
#pragma unroll
        for (int b = 0; b < 3; b++)
            tmp[a][b] = __fmul_rn(R[a][b], d[b]);

    float M[3][3];
#pragma unroll
    for (int a = 0; a < 3; a++)
#pragma unroll
        for (int cc = 0; cc < 3; cc++)
            M[a][cc] = __fadd_rn(__fadd_rn(__fmul_rn(tmp[a][0], R[cc][0]),
                                           __fmul_rn(tmp[a][1], R[cc][1])),
                                 __fmul_rn(tmp[a][2], R[cc][2]));

    float* oA = g_params + c * 12;
    oA[0] = centers[c * 3 + 0];
    oA[1] = centers[c * 3 + 1];
    oA[2] = centers[c * 3 + 2];
    oA[3]  = M[0][0];
    oA[4]  = M[1][0]; oA[5]  = M[2][0]; oA[6]  = M[0][1]; oA[7]  = M[1][1];
    oA[8]  = M[2][1]; oA[9]  = M[0][2]; oA[10] = M[1][2]; oA[11] = M[2][2];
}

// ---------------------------------------------------------------------------
// u32 sorting network, ascending — each CE is 2x IMNMX. All static indexing.
// ---------------------------------------------------------------------------
__device__ __forceinline__ void ce_asc(u32& a, u32& b) {
    u32 lo = min(a, b);
    u32 hi = max(a, b);
    a = lo; b = hi;
}

__device__ __forceinline__ void sort16_asc(u32 v[16]) {
#pragma unroll
    for (int p = 1; p < 16; p <<= 1) {
#pragma unroll
        for (int k = p; k >= 1; k >>= 1) {
#pragma unroll
            for (int j = k & (p - 1); j + k < 16; j += 2 * k) {
#pragma unroll
                for (int i = 0; i < k && (i + j + k) < 16; i++) {
                    if (((i + j) / (2 * p)) == ((i + j + k) / (2 * p))) {
                        ce_asc(v[i + j], v[i + j + k]);
                    }
                }
            }
        }
    }
}

// R asc, C asc -> R = 16 smallest of union; (r17, r18) = two smallest
// discarded keys (streaming branchless insert). Cleanup re-sorts R.
__device__ __forceinline__ void merge16_asc(u32 R[16], const u32 C[16],
                                            u32& r17, u32& r18) {
#pragma unroll
    for (int i = 0; i < 16; i++) {
        u32 b = C[15 - i];
        u32 mx = max(R[i], b);
        R[i] = min(R[i], b);
        u32 t = max(r17, mx);
        r17 = min(r17, mx);
        r18 = min(r18, t);
    }
#pragma unroll
    for (int d = 8; d >= 1; d >>= 1) {
#pragma unroll
        for (int i = 0; i < 16; i++) {
            if ((i & d) == 0) ce_asc(R[i], R[i + d]);
        }
    }
}

__device__ __forceinline__ float ex2_fast(float x) {
    float r;
    asm("ex2.approx.f32 %0, %1;" : "=f"(r) : "f"(x));
    return r;
}

// Quadratic form — bit-identical grouping to all passing kernels (FROZEN).
__device__ __forceinline__ float quadA(const float4* sA, int c,
                                       float x, float y, float z) {
    float4 a0 = sA[c * 3 + 0];
    float4 a1 = sA[c * 3 + 1];
    float4 a2 = sA[c * 3 + 2];
    float dx = x - a0.x, dy = y - a0.y, dz = z - a0.z;
    float t0 = fmaf(dz, a1.y, fmaf(dy, a1.x, __fmul_rn(dx, a0.w)));
    float t1 = fmaf(dz, a2.x, fmaf(dy, a1.w, __fmul_rn(dx, a1.z)));
    float t2 = fmaf(dz, a2.w, fmaf(dy, a2.z, __fmul_rn(dx, a2.y)));
    return __fadd_rn(__fadd_rn(__fmul_rn(t0, dx), __fmul_rn(t1, dy)),
                     __fmul_rn(t2, dz));
}

// ---------------------------------------------------------------------------
// Main: TWO threads per point. Each handles 64 centers (4 sorted batches),
// then a register shfl pair-merge yields the same top-16 set / r17 / r18 / tq
// as the single-thread version. Each thread statically owns 8 selected
// entries (bitonic-min halves partition the set) and gathers them; a 5-shfl
// pair reduction produces the output.
// ---------------------------------------------------------------------------
__global__ void __launch_bounds__(TPB, 7)
main_kernel(const float* __restrict__ xyz,
            const float4* __restrict__ rgbs,
            const float* __restrict__ dists,
            const float* __restrict__ centers,
            float* __restrict__ out, int out_size) {
    __shared__ float4 sA[NC * 3];                           // 6 KB
    __shared__ __align__(16) unsigned char slist[TPB * 16]; // 2 KB (rare path)
    __shared__ float sqv[TPB * 16];                         // 8 KB (rare path)
    __shared__ u64 sbucket[TPB * 8];                        // 8 KB (rare path)
    __shared__ float sred[TPB];
    __shared__ bool sLast;

    int tid = threadIdx.x;
#pragma unroll
    for (int i = tid; i < NC * 3; i += TPB)
        sA[i] = reinterpret_cast<const float4*>(g_params)[i];
    __syncthreads();

    int half = tid & 1;
    int p = blockIdx.x * PPB + (tid >> 1);
    float x = xyz[3 * p + 0];
    float y = xyz[3 * p + 1];
    float z = xyz[3 * p + 2];

    u32 R[16];
    u32 r17 = 0xFFFFFFFFu, r18 = 0xFFFFFFFFu;
    float pen = 0.0f;
    const float CEXP = -0.72134752044448170f;  // -0.5*log2(e)
    const float K_ADD = 2.3219280948873623f;   // log2(5)

    // ---- Pass 1 (my 64 centers): q, pen, sorted (truncq|idx) keys ----
#pragma unroll 1
    for (int b = 0; b < 4; b++) {
        u32 C[16];
#pragma unroll
        for (int j = 0; j < 16; j++) {
            int c = half * 64 + b * 16 + j;
            float q = quadA(sA, c, x, y, z);
            float e = ex2_fast(fmaf(q, CEXP, K_ADD));
            pen += fmaxf(e - 0.01f, 0.0f);
            u32 qb = __float_as_uint(fmaxf(q, 0.0f));
            C[j] = (qb & 0xFFFFFF80u) | (u32)c;
        }
        sort16_asc(C);
        if (b == 0) {
#pragma unroll
            for (int i = 0; i < 16; i++) R[i] = C[i];
        } else {
            merge16_asc(R, C, r17, r18);
        }
    }

    // ---- Pair merge via shfl-xor(1): set/r17/r18 identical to sequential ----
    u32 Bo[16];
#pragma unroll
    for (int i = 0; i < 16; i++)
        Bo[i] = __shfl_xor_sync(0xFFFFFFFFu, R[15 - i], 1);
    {
        u32 r17o = __shfl_xor_sync(0xFFFFFFFFu, r17, 1);
        u32 r18o = __shfl_xor_sync(0xFFFFFFFFu, r18, 1);
        u32 t = max(r17, r17o);
        r17 = min(r17, r17o);
        r18 = min(min(r18, r18o), t);
    }
#pragma unroll
    for (int i = 0; i < 16; i++) {
        u32 mx = max(R[i], Bo[i]);
        R[i] = min(R[i], Bo[i]);
        u32 t = max(r17, mx);
        r17 = min(r17, mx);
        r18 = min(r18, t);
    }
    // After the min-step (no cleanup): thread a's R[0..7] and thread b's
    // R[0..7] exactly partition the top-16 set (b's R[i] = a's R[15-i]).

    // boundary key via max-tree over the full set (identical in both threads
    // after combining halves via shfl)
    u32 tq = R[0];
#pragma unroll
    for (int i = 1; i < 16; i++) tq = max(tq, R[i]);
    tq = max(tq, __shfl_xor_sync(0xFFFFFFFFu, tq, 1));
    u32 btr = tq & 0xFFFFFF80u;

    // ---- Exact q for MY 8 entries (static register arrays) ----
    u32 creg[8];
    float qreg[8];
    u64 kmax = 0;
    u32 posmax = 0;
#pragma unroll
    for (int i = 0; i < 8; i++) {
        u32 c = R[i] & 0x7Fu;
        float q = quadA(sA, (int)c, x, y, z);
        float qc = fmaxf(q, 0.0f);
        creg[i] = c;
        qreg[i] = qc;
        u64 K = ((u64)__float_as_uint(qc) << 7) | c;
        bool inb = (R[i] & 0xFFFFFF80u) == btr;
        u64 Km = inb ? K : 0ull;
        bool gt = Km > kmax;
        kmax = gt ? Km : kmax;
        posmax = gt ? (u32)i : posmax;
    }
    u64 kox = __shfl_xor_sync(0xFFFFFFFFu, kmax, 1);
    u64 kmaxg = kmax > kox ? kmax : kox;
    bool mineMax = kmax > kox;   // keys unique (index bits) except both-zero

    bool tie17 = ((r17 ^ tq) & 0xFFFFFF80u) == 0u;
    bool tie18 = ((r18 ^ tq) & 0xFFFFFF80u) == 0u;

    if (tie17 && !tie18) {
        // single outside candidate: r17's center — predicated static swap
        u32 c17 = r17 & 0x7Fu;
        float q17 = quadA(sA, (int)c17, x, y, z);
        float qc17 = fmaxf(q17, 0.0f);
        u64 K17 = ((u64)__float_as_uint(qc17) << 7) | c17;
        bool swap = (K17 < kmaxg) && mineMax;
#pragma unroll
        for (int i = 0; i < 8; i++) {
            bool sel = swap && ((u32)i == posmax);
            creg[i] = sel ? c17 : creg[i];
            qreg[i] = sel ? qc17 : qreg[i];
        }
    } else if (tie17 && tie18) {
        // ---- Very rare: full exact rescan + in-bucket selection (smem) ----
        unsigned char* ml = slist + tid * 16;
        float* qv = sqv + tid * 16;
        u64* myb = sbucket + tid * 8;
        int m = 0, nb = 0;
#pragma unroll 1
        for (int c = 0; c < NC; c++) {
            float q = quadA(sA, c, x, y, z);
            float qc = fmaxf(q, 0.0f);
            u32 qb = __float_as_uint(qc);
            u32 t = qb & 0xFFFFFF80u;
            if (t < btr) {
                ml[m] = (unsigned char)c;
                qv[m] = qc;
                m++;
            } else if (t == btr && nb < 8) {
                myb[nb] = (((u64)qb << 7) | (u32)c) + 1ull;
                nb++;
            }
        }
        u64 prev = 0ull;
#pragma unroll 1
        for (int r = m; r < 16; r++) {
            u64 best = ~0ull;
#pragma unroll 1
            for (int i = 0; i < nb; i++) {
                u64 k = myb[i];
                if (k > prev && k < best) best = k;
            }
            prev = best;
            u64 bm1 = best - 1ull;
            ml[r] = (unsigned char)(bm1 & 0x7Fu);
            qv[r] = __uint_as_float((u32)(bm1 >> 7));
        }
        // take my 8 of the full list (dynamic smem index: fine)
#pragma unroll
        for (int i = 0; i < 8; i++) {
            creg[i] = (u32)ml[half * 8 + i];
            qreg[i] = qv[half * 8 + i];
        }
    }

    // ---- Gather my 8; pair-reduce via shfl ----
    float dp = dists[p];
    const float LOG2E = 1.4426950408889634f;
    float sumw = 0.0f;
    float o0 = 0.0f, o1 = 0.0f, o2 = 0.0f, o3 = 0.0f;
#pragma unroll
    for (int i = 0; i < 8; i++) {
        float w = __fmul_rn(5.0f, ex2_fast(__fmul_rn(qreg[i], CEXP)));
        w = (w >= 0.01f) ? w : 0.0f;
        sumw += w;
        if (w > 0.0f) {
            float4 g = __ldg(&rgbs[(size_t)creg[i] * NP + p]);
            float alpha = 1.0f - ex2_fast(fmaxf(g.w, 0.0f) * dp * (-LOG2E));
            o0 = fmaf(w, g.x, o0);
            o1 = fmaf(w, g.y, o1);
            o2 = fmaf(w, g.z, o2);
            o3 = fmaf(w, alpha, o3);
        }
    }
    sumw += __shfl_xor_sync(0xFFFFFFFFu, sumw, 1);
    o0 += __shfl_xor_sync(0xFFFFFFFFu, o0, 1);
    o1 += __shfl_xor_sync(0xFFFFFFFFu, o1, 1);
    o2 += __shfl_xor_sync(0xFFFFFFFFu, o2, 1);
    o3 += __shfl_xor_sync(0xFFFFFFFFu, o3, 1);
    if (half == 0) {
        float inv = __fdiv_rn(1.0f, __fadd_rn(sumw, 1e-7f));
        reinterpret_cast<float4*>(out)[p] =
            make_float4(o0 * inv, o1 * inv, o2 * inv, o3 * inv);
    }

    // ---- deterministic block reduction of penalty ----
    sred[tid] = pen;
    __syncthreads();
#pragma unroll
    for (int s = TPB / 2; s > 0; s >>= 1) {
        if (tid < s) sred[tid] += sred[tid + s];
        __syncthreads();
    }
    if (tid == 0) {
        g_partial[blockIdx.x] = sred[0];
        __threadfence();
        u32 old = atomicInc(&g_done, NBLK - 1);
        sLast = (old == NBLK - 1);
    }
    __syncthreads();

    // ---- Last block: finalize pen (deterministic fixed-order sum) ----
    if (sLast) {
        __shared__ double sd[TPB];
        double s = 0.0;
#pragma unroll
        for (int i = 0; i < NBLK / TPB; i++)
            s += (double)g_partial[tid * (NBLK / TPB) + i];
        sd[tid] = s;
        __syncthreads();
        if (tid == 0) {
            double tot = 0.0;
            for (int i = 0; i < TPB; i++) tot += sd[i];
            float bbox = 0.0f;
            for (int i = 0; i < NC * 3; i++) {
                float val = centers[i];
                bbox += fmaxf(val - 0.5f, 0.0f) + fmaxf(-0.5f - val, 0.0f);
            }
            float pv = (float)(0.001 * tot / (double)NP) + bbox;
            if (out_size > 4 * NP) {
                out[4 * NP] = pv;
                out[out_size - 1] = pv;
            }
        }
    }
}

// ---------------------------------------------------------------------------
extern "C" void kernel_launch(void* const* d_in, const int* in_sizes, int n_in,
                              void* d_out, int out_size) {
    const float* xyz = nullptr;
    const float* dists = nullptr;
    const float4* rgbs = nullptr;
    const float* small3[3] = {nullptr, nullptr, nullptr};
    int nsmall = 0;
    for (int i = 0; i < n_in; i++) {
        int sz = in_sizes[i];
        if (sz == NP * 3)                xyz   = (const float*)d_in[i];
        else if (sz == NC * NP * 4)      rgbs  = (const float4*)d_in[i];
        else if (sz == NP)               dists = (const float*)d_in[i];
        else if (sz == NC * 3 && nsmall < 3) small3[nsmall++] = (const float*)d_in[i];
    }
    const float* centers = small3[0];
    const float* radii   = small3[1];
    const float* rots    = small3[2];

    setup_kernel<<<NC, 8>>>(centers, radii, rots);
    main_kernel<<<NBLK, TPB>>>(xyz, rgbs, dists, centers, (float*)d_out, out_size);
}